// round 2
// baseline (speedup 1.0000x reference)
#include <cuda_runtime.h>

#define Bq 8192
#define Dm 1024
#define NBR 7

typedef unsigned long long u64;

// ---------- scratch (device globals; no allocations allowed) ----------
__device__ float g_Q[NBR * Dm];                         // qh per branch
__device__ float g_S[NBR * 16 * Dm];                    // score vectors s[ih][k]
__device__ float g_SC[(size_t)4 * Bq * 112];            // raw scores [v][b][ih]
__device__ float g_A[(size_t)NBR * 4 * Bq * 16];        // attn [i][l][b][h]
__device__ float g_V[(size_t)19 * Bq * Dm];             // v-proj per (branch,vec) pair
__device__ float g_O[(size_t)NBR * Bq * Dm];            // attention output o

__constant__ int c_nvec[NBR] = {2,2,2,3,3,3,4};
__constant__ int c_vidx[NBR][4] = {{0,1,0,0},{0,2,0,0},{0,3,0,0},{0,1,2,0},{0,1,3,0},{0,2,3,0},{0,1,2,3}};
__constant__ int c_poff[NBR] = {0,2,4,6,9,12,15};
__constant__ int c_pairi[19] = {0,0,1,1,2,2,3,3,3,4,4,4,5,5,5,6,6,6,6};
__constant__ int c_pairv[19] = {0,1,0,2,0,3,0,1,2,0,1,3,0,2,3,0,1,2,3};

// ---------- f32x2 helpers (Blackwell FFMA2) ----------
__device__ __forceinline__ u64 pk(float lo, float hi) {
  u64 r; asm("mov.b64 %0, {%1,%2};" : "=l"(r) : "f"(lo), "f"(hi)); return r;
}
__device__ __forceinline__ void fma2(u64& d, u64 a, u64 b) {
  asm("fma.rn.f32x2 %0, %1, %2, %0;" : "+l"(d) : "l"(a), "l"(b));
}
__device__ __forceinline__ void upk(u64 v, float& a, float& b) {
  asm("mov.b64 {%0,%1}, %2;" : "=f"(a), "=f"(b) : "l"(v));
}

// ======================================================================
// qh[i] = Wq_i @ tok_i + bq_i
// ======================================================================
__global__ void k_qh(const float* __restrict__ tokens, const float* __restrict__ w_in,
                     const float* __restrict__ b_in) {
  int i = blockIdx.x, t = threadIdx.x;
  __shared__ float tok[Dm];
  for (int k = t; k < Dm; k += 256) tok[k] = tokens[i * Dm + k];
  __syncthreads();
  const float* wq = w_in + (size_t)i * 3 * Dm * Dm;
  for (int r = t; r < Dm; r += 256) {
    const float* row = wq + (size_t)r * Dm;
    float acc = b_in[i * 3 * Dm + r];
    for (int k = 0; k < Dm; k += 4) {
      float4 w = *(const float4*)(row + k);
      acc += w.x*tok[k] + w.y*tok[k+1] + w.z*tok[k+2] + w.w*tok[k+3];
    }
    g_Q[i * Dm + r] = acc;
  }
}

// ======================================================================
// s[i*16+h][k] = (1/8) * sum_j Wk_i[h*64+j][k] * qh_i[h*64+j]
// ======================================================================
__global__ void k_s(const float* __restrict__ w_in) {
  int i = blockIdx.x, kb = blockIdx.y * 128;
  __shared__ float qh[Dm];
  for (int k = threadIdx.x; k < Dm; k += 256) qh[k] = g_Q[i * Dm + k];
  __syncthreads();
  const float* wk = w_in + (size_t)i * 3 * Dm * Dm + (size_t)Dm * Dm;
  for (int o = threadIdx.x; o < 16 * 128; o += 256) {
    int h = o >> 7, k = kb + (o & 127);
    float acc = 0.f;
    #pragma unroll 8
    for (int j = 0; j < 64; j++) acc += wk[(size_t)(h * 64 + j) * Dm + k] * qh[h * 64 + j];
    g_S[(i * 16 + h) * Dm + k] = 0.125f * acc;
  }
}

// ======================================================================
// scores: SC[v][b][ih] = x_v[b] . s[ih]   (M=8192 x N=112 x K=1024, per v)
// ======================================================================
__global__ void __launch_bounds__(256) k_scores(const float* __restrict__ xc,
    const float* __restrict__ xf, const float* __restrict__ xbd, const float* __restrict__ xbg) {
  const int v = blockIdx.y;
  const float* x = (v == 0) ? xc : (v == 1) ? xf : (v == 2) ? xbd : xbg;
  const int b0 = blockIdx.x * 128;
  __shared__ float xs[16][132];
  __shared__ float ss[16][116];
  const int t = threadIdx.x;
  const int tr = t >> 4, tc = t & 15;
  float acc[8][7];
  #pragma unroll
  for (int r = 0; r < 8; r++)
    #pragma unroll
    for (int c = 0; c < 7; c++) acc[r][c] = 0.f;

  for (int k0 = 0; k0 < Dm; k0 += 16) {
    #pragma unroll
    for (int it = 0; it < 8; it++) {
      int idx = t + it * 256;
      int row = idx >> 4, kk = idx & 15;
      xs[kk][row] = x[(size_t)(b0 + row) * Dm + k0 + kk];
    }
    for (int idx = t; idx < 112 * 16; idx += 256) {
      int col = idx >> 4, kk = idx & 15;
      ss[kk][col] = g_S[col * Dm + k0 + kk];
    }
    __syncthreads();
    #pragma unroll
    for (int kk = 0; kk < 16; kk++) {
      float4 a0 = *(const float4*)&xs[kk][tr * 8];
      float4 a1 = *(const float4*)&xs[kk][tr * 8 + 4];
      float ar[8] = {a0.x, a0.y, a0.z, a0.w, a1.x, a1.y, a1.z, a1.w};
      float bb[7];
      #pragma unroll
      for (int c = 0; c < 7; c++) bb[c] = ss[kk][tc * 7 + c];
      #pragma unroll
      for (int r = 0; r < 8; r++)
        #pragma unroll
        for (int c = 0; c < 7; c++) acc[r][c] += ar[r] * bb[c];
    }
    __syncthreads();
  }
  #pragma unroll
  for (int r = 0; r < 8; r++)
    #pragma unroll
    for (int c = 0; c < 7; c++)
      g_SC[((size_t)v * Bq + b0 + tr * 8 + r) * 112 + tc * 7 + c] = acc[r][c];
}

// ======================================================================
// softmax over L in {2,3,4} -> g_A[i][l][b][h]
// ======================================================================
__global__ void k_softmax() {
  int idx = blockIdx.x * 256 + threadIdx.x;   // 7 * 8192 * 16
  int h = idx & 15;
  int b = (idx >> 4) & (Bq - 1);
  int i = idx >> 17;
  int L = c_nvec[i];
  float sc[4];
  float mx = -1e30f;
  #pragma unroll
  for (int l = 0; l < 4; l++) if (l < L) {
    sc[l] = g_SC[((size_t)c_vidx[i][l] * Bq + b) * 112 + i * 16 + h];
    mx = fmaxf(mx, sc[l]);
  }
  float sum = 0.f;
  #pragma unroll
  for (int l = 0; l < 4; l++) if (l < L) { sc[l] = expf(sc[l] - mx); sum += sc[l]; }
  float inv = 1.f / sum;
  #pragma unroll
  for (int l = 0; l < 4; l++) if (l < L)
    g_A[(((size_t)i * 4 + l) * Bq + b) * 16 + h] = sc[l] * inv;
}

// ======================================================================
// NT GEMM: C[8192,1024] = A[8192,1024] @ W[1024,1024]^T (+bias)
// MODE 0: v-projections (z = pair 0..18)   MODE 1: out-proj (z = branch 0..6)
// 128x128 block tile, 8x8/thread via f32x2
// ======================================================================
template<int MODE>
__global__ void __launch_bounds__(256) k_gemm(
    const float* __restrict__ xc, const float* __restrict__ xf,
    const float* __restrict__ xbd, const float* __restrict__ xbg,
    const float* __restrict__ w_in, const float* __restrict__ w_out,
    const float* __restrict__ b_out, float* __restrict__ dout) {
  const float *A, *W, *bias = nullptr;
  float* C;
  if (MODE == 0) {
    int p = blockIdx.z;
    int v = c_pairv[p];
    A = (v == 0) ? xc : (v == 1) ? xf : (v == 2) ? xbd : xbg;
    W = w_in + ((size_t)c_pairi[p] * 3 + 2) * Dm * Dm;
    C = g_V + (size_t)p * Bq * Dm;
  } else {
    int i = blockIdx.z;
    A = g_O + (size_t)i * Bq * Dm;
    W = w_out + (size_t)i * Dm * Dm;
    C = dout + (size_t)i * Bq * Dm;
    bias = b_out + i * Dm;
  }
  __shared__ float As[16][132];
  __shared__ float Bs[16][132];
  const int tid = threadIdx.x;
  const int tx = tid & 15, ty = tid >> 4;
  const int lr = tid >> 2, lk = (tid & 3) * 4;
  const float* Ag = A + (size_t)(blockIdx.x * 128 + lr) * Dm + lk;
  const float* Wg = W + (size_t)(blockIdx.y * 128 + lr) * Dm + lk;
  u64 acc[8][4];
  #pragma unroll
  for (int r = 0; r < 8; r++)
    #pragma unroll
    for (int c = 0; c < 4; c++) acc[r][c] = 0ULL;

  for (int kt = 0; kt < Dm; kt += 16) {
    float4 a0 = *(const float4*)(Ag + kt);
    float4 a1 = *(const float4*)(Ag + kt + (size_t)64 * Dm);
    float4 w0 = *(const float4*)(Wg + kt);
    float4 w1 = *(const float4*)(Wg + kt + (size_t)64 * Dm);
    __syncthreads();
    As[lk+0][lr] = a0.x; As[lk+1][lr] = a0.y; As[lk+2][lr] = a0.z; As[lk+3][lr] = a0.w;
    As[lk+0][lr+64] = a1.x; As[lk+1][lr+64] = a1.y; As[lk+2][lr+64] = a1.z; As[lk+3][lr+64] = a1.w;
    Bs[lk+0][lr] = w0.x; Bs[lk+1][lr] = w0.y; Bs[lk+2][lr] = w0.z; Bs[lk+3][lr] = w0.w;
    Bs[lk+0][lr+64] = w1.x; Bs[lk+1][lr+64] = w1.y; Bs[lk+2][lr+64] = w1.z; Bs[lk+3][lr+64] = w1.w;
    __syncthreads();
    #pragma unroll
    for (int k = 0; k < 16; k++) {
      float4 av0 = *(const float4*)&As[k][ty * 8];
      float4 av1 = *(const float4*)&As[k][ty * 8 + 4];
      u64 bp[4];
      bp[0] = *(const u64*)&Bs[k][tx * 8];
      bp[1] = *(const u64*)&Bs[k][tx * 8 + 2];
      bp[2] = *(const u64*)&Bs[k][tx * 8 + 4];
      bp[3] = *(const u64*)&Bs[k][tx * 8 + 6];
      float ar[8] = {av0.x, av0.y, av0.z, av0.w, av1.x, av1.y, av1.z, av1.w};
      #pragma unroll
      for (int r = 0; r < 8; r++) {
        u64 ap = pk(ar[r], ar[r]);
        #pragma unroll
        for (int c = 0; c < 4; c++) fma2(acc[r][c], ap, bp[c]);
      }
    }
  }
  const int m0 = blockIdx.x * 128 + ty * 8;
  const int n0 = blockIdx.y * 128 + tx * 8;
  float bb[8];
  #pragma unroll
  for (int c = 0; c < 8; c++) bb[c] = (MODE == 1) ? bias[n0 + c] : 0.f;
  #pragma unroll
  for (int r = 0; r < 8; r++) {
    float o[8];
    #pragma unroll
    for (int c = 0; c < 4; c++) upk(acc[r][c], o[2*c], o[2*c+1]);
    #pragma unroll
    for (int c = 0; c < 8; c++) o[c] += bb[c];
    float4* dst = (float4*)(C + (size_t)(m0 + r) * Dm + n0);
    dst[0] = make_float4(o[0], o[1], o[2], o[3]);
    dst[1] = make_float4(o[4], o[5], o[6], o[7]);
  }
}

// ======================================================================
// mix: o[i][b][k] = bv_i[k] + sum_l a[i][l][b][k>>6] * vproj[p][b][k]
// ======================================================================
__global__ void k_mix(const float* __restrict__ b_in) {
  size_t gid = (size_t)blockIdx.x * 256 + threadIdx.x;   // 7 * 8192 * 256 float4s
  int i = (int)(gid >> 21);
  int rem = (int)(gid & ((1u << 21) - 1));
  int b = rem >> 8;
  int k = (rem & 255) * 4;
  int h = k >> 6;
  int L = c_nvec[i];
  int p0 = c_poff[i];
  float4 o = *(const float4*)(b_in + ((size_t)i * 3 + 2) * Dm + k);
  #pragma unroll
  for (int l = 0; l < 4; l++) if (l < L) {
    float a = g_A[(((size_t)i * 4 + l) * Bq + b) * 16 + h];
    float4 vv = *(const float4*)(g_V + ((size_t)(p0 + l) * Bq + b) * Dm + k);
    o.x += a * vv.x; o.y += a * vv.y; o.z += a * vv.z; o.w += a * vv.w;
  }
  *(float4*)(g_O + ((size_t)i * Bq + b) * Dm + k) = o;
}

// ======================================================================
extern "C" void kernel_launch(void* const* d_in, const int* in_sizes, int n_in,
                              void* d_out, int out_size) {
  const float* xc     = (const float*)d_in[0];
  const float* xf     = (const float*)d_in[1];
  const float* xbd    = (const float*)d_in[2];
  const float* xbg    = (const float*)d_in[3];
  const float* tokens = (const float*)d_in[4];
  const float* w_in   = (const float*)d_in[5];
  const float* b_in   = (const float*)d_in[6];
  const float* w_out  = (const float*)d_in[7];
  const float* b_out  = (const float*)d_in[8];
  float* out = (float*)d_out;

  k_qh<<<NBR, 256>>>(tokens, w_in, b_in);
  k_s<<<dim3(NBR, 8), 256>>>(w_in);
  k_scores<<<dim3(Bq / 128, 4), 256>>>(xc, xf, xbd, xbg);
  k_softmax<<<NBR * Bq * 16 / 256, 256>>>();
  k_gemm<0><<<dim3(Bq / 128, Dm / 128, 19), 256>>>(xc, xf, xbd, xbg, w_in, w_out, b_out, out);
  k_mix<<<NBR * Bq * (Dm / 4) / 256, 256>>>(b_in);
  k_gemm<1><<<dim3(Bq / 128, Dm / 128, NBR), 256>>>(xc, xf, xbd, xbg, w_in, w_out, b_out, out);
}

// round 4
// speedup vs baseline: 1.8633x; 1.8633x over previous
#include <cuda_runtime.h>
#include <cuda_bf16.h>
#include <cstdint>

#define Bq 8192
#define Dm 1024
#define NBR 7
#define BD ((size_t)Bq * Dm)
#define DD ((size_t)Dm * Dm)

// ---------------- scratch ----------------
__device__ float g_Q[NBR * Dm];
__device__ float g_S[NBR * 16 * Dm];
__device__ float g_SC[(size_t)4 * Bq * 112];
__device__ float g_A[(size_t)NBR * 4 * Bq * 16];
__device__ float g_V[(size_t)19 * BD];
__device__ float g_O[(size_t)NBR * BD];
__device__ __nv_bfloat16 g_Ah[4 * BD];
__device__ __nv_bfloat16 g_Al[4 * BD];
__device__ __nv_bfloat16 g_Wh[14 * DD];
__device__ __nv_bfloat16 g_Wl[14 * DD];
__device__ __nv_bfloat16 g_Oh[NBR * BD];
__device__ __nv_bfloat16 g_Ol[NBR * BD];

__constant__ int c_nvec[NBR] = {2,2,2,3,3,3,4};
__constant__ int c_vidx[NBR][4] = {{0,1,0,0},{0,2,0,0},{0,3,0,0},{0,1,2,0},{0,1,3,0},{0,2,3,0},{0,1,2,3}};
__constant__ int c_poff[NBR] = {0,2,4,6,9,12,15};
__constant__ int c_pairi[19] = {0,0,1,1,2,2,3,3,3,4,4,4,5,5,5,6,6,6,6};
__constant__ int c_pairv[19] = {0,1,0,2,0,3,0,1,2,0,1,3,0,2,3,0,1,2,3};

// ---------------- PTX helpers (all plain-sm_103-legal) ----------------
__device__ __forceinline__ uint32_t smem_u32(const void* p) {
  uint32_t a;
  asm("{ .reg .u64 t; cvta.to.shared.u64 t, %1; cvt.u32.u64 %0, t; }" : "=r"(a) : "l"(p));
  return a;
}
__device__ __forceinline__ void cpa16(uint32_t s, const void* g) {
  asm volatile("cp.async.cg.shared.global [%0], [%1], 16;" :: "r"(s), "l"(g) : "memory");
}
#define CP_COMMIT() asm volatile("cp.async.commit_group;" ::: "memory")
#define CP_WAIT2()  asm volatile("cp.async.wait_group 2;" ::: "memory")

__device__ __forceinline__ void ldsm4(uint32_t& r0, uint32_t& r1, uint32_t& r2, uint32_t& r3, uint32_t addr) {
  asm volatile("ldmatrix.sync.aligned.m8n8.x4.shared.b16 {%0,%1,%2,%3}, [%4];"
               : "=r"(r0), "=r"(r1), "=r"(r2), "=r"(r3) : "r"(addr));
}
__device__ __forceinline__ void mma16816(float* c, const uint32_t* a, const uint32_t* b) {
  asm volatile("mma.sync.aligned.m16n8k16.row.col.f32.bf16.bf16.f32 "
               "{%0,%1,%2,%3}, {%4,%5,%6,%7}, {%8,%9}, {%0,%1,%2,%3};"
               : "+f"(c[0]), "+f"(c[1]), "+f"(c[2]), "+f"(c[3])
               : "r"(a[0]), "r"(a[1]), "r"(a[2]), "r"(a[3]), "r"(b[0]), "r"(b[1]));
}

// ======================= small prep kernels =======================
__global__ void k_qh(const float* __restrict__ tokens, const float* __restrict__ w_in,
                     const float* __restrict__ b_in) {
  int i = blockIdx.x, t = threadIdx.x;
  __shared__ float tok[Dm];
  for (int k = t; k < Dm; k += 256) tok[k] = tokens[i * Dm + k];
  __syncthreads();
  const float* wq = w_in + (size_t)i * 3 * DD;
  for (int r = t; r < Dm; r += 256) {
    const float* row = wq + (size_t)r * Dm;
    float acc = b_in[i * 3 * Dm + r];
    for (int k = 0; k < Dm; k += 4) {
      float4 w = *(const float4*)(row + k);
      acc += w.x*tok[k] + w.y*tok[k+1] + w.z*tok[k+2] + w.w*tok[k+3];
    }
    g_Q[i * Dm + r] = acc;
  }
}

__global__ void k_s(const float* __restrict__ w_in) {
  int i = blockIdx.x, kb = blockIdx.y * 128;
  __shared__ float qh[Dm];
  for (int k = threadIdx.x; k < Dm; k += 256) qh[k] = g_Q[i * Dm + k];
  __syncthreads();
  const float* wk = w_in + (size_t)i * 3 * DD + DD;
  for (int o = threadIdx.x; o < 16 * 128; o += 256) {
    int h = o >> 7, k = kb + (o & 127);
    float acc = 0.f;
    #pragma unroll 8
    for (int j = 0; j < 64; j++) acc += wk[(size_t)(h * 64 + j) * Dm + k] * qh[h * 64 + j];
    g_S[(i * 16 + h) * Dm + k] = 0.125f * acc;
  }
}

__global__ void __launch_bounds__(256) k_scores(const float* __restrict__ xc,
    const float* __restrict__ xf, const float* __restrict__ xbd, const float* __restrict__ xbg) {
  const int v = blockIdx.y;
  const float* x = (v == 0) ? xc : (v == 1) ? xf : (v == 2) ? xbd : xbg;
  const int b0 = blockIdx.x * 128;
  __shared__ float xs[16][132];
  __shared__ float ss[16][116];
  const int t = threadIdx.x;
  const int tr = t >> 4, tc = t & 15;
  float acc[8][7];
  #pragma unroll
  for (int r = 0; r < 8; r++)
    #pragma unroll
    for (int c = 0; c < 7; c++) acc[r][c] = 0.f;
  for (int k0 = 0; k0 < Dm; k0 += 16) {
    #pragma unroll
    for (int it = 0; it < 8; it++) {
      int idx = t + it * 256;
      int row = idx >> 4, kk = idx & 15;
      xs[kk][row] = x[(size_t)(b0 + row) * Dm + k0 + kk];
    }
    for (int idx = t; idx < 112 * 16; idx += 256) {
      int col = idx >> 4, kk = idx & 15;
      ss[kk][col] = g_S[col * Dm + k0 + kk];
    }
    __syncthreads();
    #pragma unroll
    for (int kk = 0; kk < 16; kk++) {
      float4 a0 = *(const float4*)&xs[kk][tr * 8];
      float4 a1 = *(const float4*)&xs[kk][tr * 8 + 4];
      float ar[8] = {a0.x, a0.y, a0.z, a0.w, a1.x, a1.y, a1.z, a1.w};
      float bb[7];
      #pragma unroll
      for (int c = 0; c < 7; c++) bb[c] = ss[kk][tc * 7 + c];
      #pragma unroll
      for (int r = 0; r < 8; r++)
        #pragma unroll
        for (int c = 0; c < 7; c++) acc[r][c] += ar[r] * bb[c];
    }
    __syncthreads();
  }
  #pragma unroll
  for (int r = 0; r < 8; r++)
    #pragma unroll
    for (int c = 0; c < 7; c++)
      g_SC[((size_t)v * Bq + b0 + tr * 8 + r) * 112 + tc * 7 + c] = acc[r][c];
}

__global__ void k_softmax() {
  int idx = blockIdx.x * 256 + threadIdx.x;
  int h = idx & 15;
  int b = (idx >> 4) & (Bq - 1);
  int i = idx >> 17;
  int L = c_nvec[i];
  float sc[4];
  float mx = -1e30f;
  #pragma unroll
  for (int l = 0; l < 4; l++) if (l < L) {
    sc[l] = g_SC[((size_t)c_vidx[i][l] * Bq + b) * 112 + i * 16 + h];
    mx = fmaxf(mx, sc[l]);
  }
  float sum = 0.f;
  #pragma unroll
  for (int l = 0; l < 4; l++) if (l < L) { sc[l] = expf(sc[l] - mx); sum += sc[l]; }
  float inv = 1.f / sum;
  #pragma unroll
  for (int l = 0; l < 4; l++) if (l < L)
    g_A[(((size_t)i * 4 + l) * Bq + b) * 16 + h] = sc[l] * inv;
}

__global__ void k_mix(const float* __restrict__ b_in) {
  size_t gid = (size_t)blockIdx.x * 256 + threadIdx.x;
  int i = (int)(gid >> 21);
  int rem = (int)(gid & ((1u << 21) - 1));
  int b = rem >> 8;
  int k = (rem & 255) * 4;
  int h = k >> 6;
  int L = c_nvec[i];
  int p0 = c_poff[i];
  float4 o = *(const float4*)(b_in + ((size_t)i * 3 + 2) * Dm + k);
  #pragma unroll
  for (int l = 0; l < 4; l++) if (l < L) {
    float a = g_A[(((size_t)i * 4 + l) * Bq + b) * 16 + h];
    float4 vv = *(const float4*)(g_V + ((size_t)(p0 + l) * Bq + b) * Dm + k);
    o.x += a * vv.x; o.y += a * vv.y; o.z += a * vv.z; o.w += a * vv.w;
  }
  *(float4*)(g_O + ((size_t)i * Bq + b) * Dm + k) = o;
}

// ======================= fp32 -> bf16 hi/lo split =======================
__device__ __forceinline__ void split4(float4 v, uint2& hi, uint2& lo) {
  __nv_bfloat16 h0 = __float2bfloat16_rn(v.x), h1 = __float2bfloat16_rn(v.y);
  __nv_bfloat16 h2 = __float2bfloat16_rn(v.z), h3 = __float2bfloat16_rn(v.w);
  __nv_bfloat16 l0 = __float2bfloat16_rn(v.x - __bfloat162float(h0));
  __nv_bfloat16 l1 = __float2bfloat16_rn(v.y - __bfloat162float(h1));
  __nv_bfloat16 l2 = __float2bfloat16_rn(v.z - __bfloat162float(h2));
  __nv_bfloat16 l3 = __float2bfloat16_rn(v.w - __bfloat162float(h3));
  __nv_bfloat162 a{h0, h1}, b{h2, h3}, c{l0, l1}, d{l2, l3};
  hi = make_uint2(*(uint32_t*)&a, *(uint32_t*)&b);
  lo = make_uint2(*(uint32_t*)&c, *(uint32_t*)&d);
}

__global__ void k_convA(const float* __restrict__ xc, const float* __restrict__ xf,
                        const float* __restrict__ xbd, const float* __restrict__ xbg) {
  int v = blockIdx.y;
  const float* x = (v == 0) ? xc : (v == 1) ? xf : (v == 2) ? xbd : xbg;
  size_t i = (size_t)blockIdx.x * 256 + threadIdx.x;
  float4 val = ((const float4*)x)[i];
  uint2 hi, lo; split4(val, hi, lo);
  ((uint2*)(g_Ah + (size_t)v * BD))[i] = hi;
  ((uint2*)(g_Al + (size_t)v * BD))[i] = lo;
}

__global__ void k_convW(const float* __restrict__ w_in, const float* __restrict__ w_out) {
  int z = blockIdx.y;
  const float* src = (z < 7) ? (w_in + (size_t)z * 3 * DD + 2 * DD) : (w_out + (size_t)(z - 7) * DD);
  size_t i = (size_t)blockIdx.x * 256 + threadIdx.x;
  float4 val = ((const float4*)src)[i];
  uint2 hi, lo; split4(val, hi, lo);
  ((uint2*)(g_Wh + (size_t)z * DD))[i] = hi;
  ((uint2*)(g_Wl + (size_t)z * DD))[i] = lo;
}

__global__ void k_convO() {
  int v = blockIdx.y;
  size_t i = (size_t)blockIdx.x * 256 + threadIdx.x;
  float4 val = ((const float4*)(g_O + (size_t)v * BD))[i];
  uint2 hi, lo; split4(val, hi, lo);
  ((uint2*)(g_Oh + (size_t)v * BD))[i] = hi;
  ((uint2*)(g_Ol + (size_t)v * BD))[i] = lo;
}

// ======================= HMMA GEMM: C[8192x1024] = A @ W^T (bf16 3-term split) =======================
// 128x128 CTA tile, 8 warps (64x32 each), K-chunks of 32, 3 segments (hi*hi, hi*lo, lo*hi),
// 3-stage cp.async pipeline. SMEM stage: A 8KB + W 8KB.
#define CHUNKS 96

__device__ __forceinline__ uint32_t sw(uint32_t row, uint32_t g) {
  // 64B rows, 4x16B granules, xor-swizzle for conflict-free ldmatrix
  return row * 64 + ((g ^ ((row >> 1) & 3)) << 4);
}

template<int MODE>
__global__ void __launch_bounds__(256, 2) k_mma(const float* __restrict__ b_out,
                                                float* __restrict__ dout) {
  __shared__ __align__(16) char smem[3 * 16384];
  const int tid = threadIdx.x;
  const int wid = tid >> 5, lane = tid & 31;
  const int m0 = blockIdx.x * 128, n0 = blockIdx.y * 128;
  const int wm = (wid & 1) * 64, wn = (wid >> 1) * 32;

  const __nv_bfloat16 *Ah, *Al, *Wh, *Wl;
  float* C; const float* bias = nullptr;
  if (MODE == 0) {
    int p = blockIdx.z;
    int v = c_pairv[p], wi = c_pairi[p];
    Ah = g_Ah + (size_t)v * BD;  Al = g_Al + (size_t)v * BD;
    Wh = g_Wh + (size_t)wi * DD; Wl = g_Wl + (size_t)wi * DD;
    C = g_V + (size_t)p * BD;
  } else {
    int i = blockIdx.z;
    Ah = g_Oh + (size_t)i * BD;  Al = g_Ol + (size_t)i * BD;
    Wh = g_Wh + (size_t)(7 + i) * DD; Wl = g_Wl + (size_t)(7 + i) * DD;
    C = dout + (size_t)i * BD;
    bias = b_out + i * Dm;
  }
  const __nv_bfloat16* Aseg[3] = {Ah, Ah, Al};
  const __nv_bfloat16* Wseg[3] = {Wh, Wl, Wh};

  const uint32_t sb = smem_u32(smem);

  float acc[4][4][4];
  #pragma unroll
  for (int mt = 0; mt < 4; mt++)
    #pragma unroll
    for (int nt = 0; nt < 4; nt++)
      #pragma unroll
      for (int r = 0; r < 4; r++) acc[mt][nt][r] = 0.f;

  // loader: each thread moves 2x16B of A and 2x16B of W per chunk
  const int gi0 = tid * 2;
  const int lrow = gi0 >> 2;
  const uint32_t soff0 = sw(lrow, gi0 & 3);
  const uint32_t soff1 = sw((gi0 + 1) >> 2, (gi0 + 1) & 3);

  #pragma unroll 1
  for (int c = 0; c < 3; c++) {
    int s = c >> 5, kc = (c & 31) * 32;
    const __nv_bfloat16* Ap = Aseg[s] + (size_t)(m0 + lrow) * Dm + kc;
    const __nv_bfloat16* Wp = Wseg[s] + (size_t)(n0 + lrow) * Dm + kc;
    uint32_t ab = sb + c * 16384;
    cpa16(ab + soff0,        Ap + (gi0 & 3) * 8);
    cpa16(ab + soff1,        Ap + ((gi0 + 1) & 3) * 8);
    cpa16(ab + 8192 + soff0, Wp + (gi0 & 3) * 8);
    cpa16(ab + 8192 + soff1, Wp + ((gi0 + 1) & 3) * 8);
    CP_COMMIT();
  }

  // precomputed ldmatrix lane geometry
  const int arow = wm + (lane & 15);          // + mt*16
  const int agsel = lane >> 4;
  const int brow = wn + ((lane & 7) | ((lane & 16) >> 1));  // + np*16
  const int bgsel = (lane >> 3) & 1;

  for (int c = 0; c < CHUNKS; c++) {
    const uint32_t ab = sb + (c % 3) * 16384;
    CP_WAIT2();
    __syncthreads();
    #pragma unroll
    for (int ks = 0; ks < 2; ks++) {
      uint32_t a[4][4], b[4][2];
      #pragma unroll
      for (int mt = 0; mt < 4; mt++) {
        uint32_t addr = ab + sw(arow + mt * 16, ks * 2 + agsel);
        ldsm4(a[mt][0], a[mt][1], a[mt][2], a[mt][3], addr);
      }
      #pragma unroll
      for (int np = 0; np < 2; np++) {
        uint32_t addr = ab + 8192 + sw(brow + np * 16, ks * 2 + bgsel);
        ldsm4(b[np*2][0], b[np*2][1], b[np*2+1][0], b[np*2+1][1], addr);
      }
      #pragma unroll
      for (int mt = 0; mt < 4; mt++)
        #pragma unroll
        for (int nt = 0; nt < 4; nt++)
          mma16816(acc[mt][nt], a[mt], b[nt]);
    }
    __syncthreads();
    int cn = c + 3;
    if (cn < CHUNKS) {
      int s = cn >> 5, kc = (cn & 31) * 32;
      const __nv_bfloat16* Ap = Aseg[s] + (size_t)(m0 + lrow) * Dm + kc;
      const __nv_bfloat16* Wp = Wseg[s] + (size_t)(n0 + lrow) * Dm + kc;
      cpa16(ab + soff0,        Ap + (gi0 & 3) * 8);
      cpa16(ab + soff1,        Ap + ((gi0 + 1) & 3) * 8);
      cpa16(ab + 8192 + soff0, Wp + (gi0 & 3) * 8);
      cpa16(ab + 8192 + soff1, Wp + ((gi0 + 1) & 3) * 8);
    }
    CP_COMMIT();   // empty group in tail keeps wait_group accounting uniform
  }

  // epilogue
  #pragma unroll
  for (int mt = 0; mt < 4; mt++) {
    int m = m0 + wm + mt * 16 + (lane >> 2);
    #pragma unroll
    for (int nt = 0; nt < 4; nt++) {
      int n = n0 + wn + nt * 8 + (lane & 3) * 2;
      float2 v0 = make_float2(acc[mt][nt][0], acc[mt][nt][1]);
      float2 v1 = make_float2(acc[mt][nt][2], acc[mt][nt][3]);
      if (MODE == 1) {
        float b0 = bias[n], b1 = bias[n + 1];
        v0.x += b0; v0.y += b1; v1.x += b0; v1.y += b1;
      }
      *(float2*)(C + (size_t)m * Dm + n) = v0;
      *(float2*)(C + (size_t)(m + 8) * Dm + n) = v1;
    }
  }
}

// ======================================================================
extern "C" void kernel_launch(void* const* d_in, const int* in_sizes, int n_in,
                              void* d_out, int out_size) {
  const float* xc     = (const float*)d_in[0];
  const float* xf     = (const float*)d_in[1];
  const float* xbd    = (const float*)d_in[2];
  const float* xbg    = (const float*)d_in[3];
  const float* tokens = (const float*)d_in[4];
  const float* w_in   = (const float*)d_in[5];
  const float* b_in   = (const float*)d_in[6];
  const float* w_out  = (const float*)d_in[7];
  const float* b_out  = (const float*)d_in[8];
  float* out = (float*)d_out;

  k_qh<<<NBR, 256>>>(tokens, w_in, b_in);
  k_s<<<dim3(NBR, 8), 256>>>(w_in);
  k_scores<<<dim3(Bq / 128, 4), 256>>>(xc, xf, xbd, xbg);
  k_softmax<<<NBR * Bq * 16 / 256, 256>>>();
  k_convA<<<dim3(Bq, 4), 256>>>(xc, xf, xbd, xbg);
  k_convW<<<dim3(1024, 14), 256>>>(w_in, w_out);
  k_mma<0><<<dim3(Bq / 128, Dm / 128, 19), 256>>>(b_out, out);
  k_mix<<<NBR * Bq * (Dm / 4) / 256, 256>>>(b_in);
  k_convO<<<dim3(Bq, NBR), 256>>>();
  k_mma<1><<<dim3(Bq / 128, Dm / 128, NBR), 256>>>(b_out, out);
}

// round 5
// speedup vs baseline: 1.9043x; 1.0220x over previous
#include <cuda_runtime.h>
#include <cuda_bf16.h>
#include <cstdint>

#define Bq 8192
#define Dm 1024
#define NBR 7
#define BD ((size_t)Bq * Dm)
#define DD ((size_t)Dm * Dm)

// ---------------- scratch ----------------
__device__ float g_Q[NBR * Dm];
__device__ float g_SC[(size_t)4 * Bq * 256];            // scores, stride 256
__device__ float g_A[(size_t)NBR * 4 * Bq * 16];
__device__ float g_V[(size_t)19 * BD];
__device__ __nv_bfloat16 g_Sh[256 * Dm];                // split score vecs (112 used, zero-pad)
__device__ __nv_bfloat16 g_Sl[256 * Dm];
__device__ __nv_bfloat16 g_Ah[4 * BD];
__device__ __nv_bfloat16 g_Al[4 * BD];
__device__ __nv_bfloat16 g_Wh[14 * DD];
__device__ __nv_bfloat16 g_Wl[14 * DD];
__device__ __nv_bfloat16 g_Oh[NBR * BD];
__device__ __nv_bfloat16 g_Ol[NBR * BD];

__constant__ int c_nvec[NBR] = {2,2,2,3,3,3,4};
__constant__ int c_vidx[NBR][4] = {{0,1,0,0},{0,2,0,0},{0,3,0,0},{0,1,2,0},{0,1,3,0},{0,2,3,0},{0,1,2,3}};
__constant__ int c_poff[NBR] = {0,2,4,6,9,12,15};
__constant__ int c_pairi[19] = {0,0,1,1,2,2,3,3,3,4,4,4,5,5,5,6,6,6,6};
__constant__ int c_pairv[19] = {0,1,0,2,0,3,0,1,2,0,1,3,0,2,3,0,1,2,3};

// ---------------- PTX helpers ----------------
__device__ __forceinline__ uint32_t smem_u32(const void* p) {
  uint32_t a;
  asm("{ .reg .u64 t; cvta.to.shared.u64 t, %1; cvt.u32.u64 %0, t; }" : "=r"(a) : "l"(p));
  return a;
}
__device__ __forceinline__ void cpa16(uint32_t s, const void* g) {
  asm volatile("cp.async.cg.shared.global [%0], [%1], 16;" :: "r"(s), "l"(g) : "memory");
}
#define CP_COMMIT() asm volatile("cp.async.commit_group;" ::: "memory")
#define CP_WAIT2()  asm volatile("cp.async.wait_group 2;" ::: "memory")

__device__ __forceinline__ void ldsm4(uint32_t& r0, uint32_t& r1, uint32_t& r2, uint32_t& r3, uint32_t addr) {
  asm volatile("ldmatrix.sync.aligned.m8n8.x4.shared.b16 {%0,%1,%2,%3}, [%4];"
               : "=r"(r0), "=r"(r1), "=r"(r2), "=r"(r3) : "r"(addr));
}
__device__ __forceinline__ void mma16816(float* c, const uint32_t* a, const uint32_t* b) {
  asm volatile("mma.sync.aligned.m16n8k16.row.col.f32.bf16.bf16.f32 "
               "{%0,%1,%2,%3}, {%4,%5,%6,%7}, {%8,%9}, {%0,%1,%2,%3};"
               : "+f"(c[0]), "+f"(c[1]), "+f"(c[2]), "+f"(c[3])
               : "r"(a[0]), "r"(a[1]), "r"(a[2]), "r"(a[3]), "r"(b[0]), "r"(b[1]));
}

// ======================= fp32 -> bf16 hi/lo split =======================
__device__ __forceinline__ void split4(float4 v, uint2& hi, uint2& lo) {
  __nv_bfloat16 h0 = __float2bfloat16_rn(v.x), h1 = __float2bfloat16_rn(v.y);
  __nv_bfloat16 h2 = __float2bfloat16_rn(v.z), h3 = __float2bfloat16_rn(v.w);
  __nv_bfloat16 l0 = __float2bfloat16_rn(v.x - __bfloat162float(h0));
  __nv_bfloat16 l1 = __float2bfloat16_rn(v.y - __bfloat162float(h1));
  __nv_bfloat16 l2 = __float2bfloat16_rn(v.z - __bfloat162float(h2));
  __nv_bfloat16 l3 = __float2bfloat16_rn(v.w - __bfloat162float(h3));
  __nv_bfloat162 a{h0, h1}, b{h2, h3}, c{l0, l1}, d{l2, l3};
  hi = make_uint2(*(uint32_t*)&a, *(uint32_t*)&b);
  lo = make_uint2(*(uint32_t*)&c, *(uint32_t*)&d);
}

// ======================= prep kernels =======================
__global__ void k_qh(const float* __restrict__ tokens, const float* __restrict__ w_in,
                     const float* __restrict__ b_in) {
  int i = blockIdx.x, t = threadIdx.x;
  __shared__ float tok[Dm];
  for (int k = t; k < Dm; k += 256) tok[k] = tokens[i * Dm + k];
  __syncthreads();
  const float* wq = w_in + (size_t)i * 3 * DD;
  for (int r = t; r < Dm; r += 256) {
    const float* row = wq + (size_t)r * Dm;
    float acc = b_in[i * 3 * Dm + r];
    for (int k = 0; k < Dm; k += 4) {
      float4 w = *(const float4*)(row + k);
      acc += w.x*tok[k] + w.y*tok[k+1] + w.z*tok[k+2] + w.w*tok[k+3];
    }
    g_Q[i * Dm + r] = acc;
  }
}

__global__ void k_s(const float* __restrict__ w_in) {
  int i = blockIdx.x, kb = blockIdx.y * 128;
  __shared__ float qh[Dm];
  for (int k = threadIdx.x; k < Dm; k += 256) qh[k] = g_Q[i * Dm + k];
  __syncthreads();
  const float* wk = w_in + (size_t)i * 3 * DD + DD;
  for (int o = threadIdx.x; o < 16 * 128; o += 256) {
    int h = o >> 7, k = kb + (o & 127);
    float acc = 0.f;
    #pragma unroll 8
    for (int j = 0; j < 64; j++) acc += wk[(size_t)(h * 64 + j) * Dm + k] * qh[h * 64 + j];
    float val = 0.125f * acc;
    __nv_bfloat16 hi = __float2bfloat16_rn(val);
    g_Sh[(i * 16 + h) * Dm + k] = hi;
    g_Sl[(i * 16 + h) * Dm + k] = __float2bfloat16_rn(val - __bfloat162float(hi));
  }
}

__global__ void k_zs() {   // zero rows 112..255 of g_Sh/g_Sl
  int row = 112 + blockIdx.x;
  for (int k = threadIdx.x; k < Dm; k += 256) {
    g_Sh[row * Dm + k] = __float2bfloat16(0.f);
    g_Sl[row * Dm + k] = __float2bfloat16(0.f);
  }
}

__global__ void k_softmax() {
  int idx = blockIdx.x * 256 + threadIdx.x;
  int h = idx & 15;
  int b = (idx >> 4) & (Bq - 1);
  int i = idx >> 17;
  int L = c_nvec[i];
  float sc[4];
  float mx = -1e30f;
  #pragma unroll
  for (int l = 0; l < 4; l++) if (l < L) {
    sc[l] = g_SC[((size_t)c_vidx[i][l] * Bq + b) * 256 + i * 16 + h];
    mx = fmaxf(mx, sc[l]);
  }
  float sum = 0.f;
  #pragma unroll
  for (int l = 0; l < 4; l++) if (l < L) { sc[l] = expf(sc[l] - mx); sum += sc[l]; }
  float inv = 1.f / sum;
  #pragma unroll
  for (int l = 0; l < 4; l++) if (l < L)
    g_A[(((size_t)i * 4 + l) * Bq + b) * 16 + h] = sc[l] * inv;
}

// mix: o = bv + sum_l a*vproj -> write bf16 hi/lo splits directly
__global__ void k_mix(const float* __restrict__ b_in) {
  size_t gid = (size_t)blockIdx.x * 256 + threadIdx.x;
  int i = (int)(gid >> 21);
  int rem = (int)(gid & ((1u << 21) - 1));
  int b = rem >> 8;
  int k = (rem & 255) * 4;
  int h = k >> 6;
  int L = c_nvec[i];
  int p0 = c_poff[i];
  float4 o = *(const float4*)(b_in + ((size_t)i * 3 + 2) * Dm + k);
  #pragma unroll
  for (int l = 0; l < 4; l++) if (l < L) {
    float a = g_A[(((size_t)i * 4 + l) * Bq + b) * 16 + h];
    float4 vv = *(const float4*)(g_V + ((size_t)(p0 + l) * Bq + b) * Dm + k);
    o.x += a * vv.x; o.y += a * vv.y; o.z += a * vv.z; o.w += a * vv.w;
  }
  uint2 hi, lo; split4(o, hi, lo);
  size_t e4 = (((size_t)i * Bq + b) * Dm + k) >> 2;
  ((uint2*)g_Oh)[e4] = hi;
  ((uint2*)g_Ol)[e4] = lo;
}

__global__ void k_convA(const float* __restrict__ xc, const float* __restrict__ xf,
                        const float* __restrict__ xbd, const float* __restrict__ xbg) {
  int v = blockIdx.y;
  const float* x = (v == 0) ? xc : (v == 1) ? xf : (v == 2) ? xbd : xbg;
  size_t i = (size_t)blockIdx.x * 256 + threadIdx.x;
  float4 val = ((const float4*)x)[i];
  uint2 hi, lo; split4(val, hi, lo);
  ((uint2*)(g_Ah + (size_t)v * BD))[i] = hi;
  ((uint2*)(g_Al + (size_t)v * BD))[i] = lo;
}

__global__ void k_convW(const float* __restrict__ w_in, const float* __restrict__ w_out) {
  int z = blockIdx.y;
  const float* src = (z < 7) ? (w_in + (size_t)z * 3 * DD + 2 * DD) : (w_out + (size_t)(z - 7) * DD);
  size_t i = (size_t)blockIdx.x * 256 + threadIdx.x;
  float4 val = ((const float4*)src)[i];
  uint2 hi, lo; split4(val, hi, lo);
  ((uint2*)(g_Wh + (size_t)z * DD))[i] = hi;
  ((uint2*)(g_Wl + (size_t)z * DD))[i] = lo;
}

// ======================= HMMA GEMM: C = A @ W^T (bf16 3-term split) =======================
// CTA tile 128(M) x 256(N), 8 warps (2x4) of 64x64, K-chunk 32, 4-stage cp.async pipeline.
// MODE 0: v-proj (z=pair)  MODE 1: out-proj (z=branch, +bias)  MODE 2: scores (z=v, W=g_S*, Cstride=256)
#define CHUNKS 96
#define STAGE 24576
#define SMEM_SZ (4 * STAGE)

__device__ __forceinline__ uint32_t sw(uint32_t row, uint32_t g) {
  return row * 64 + ((g ^ ((row >> 1) & 3)) << 4);
}

template<int MODE>
__global__ void __launch_bounds__(256, 1) k_mma(const float* __restrict__ b_out,
                                                float* __restrict__ dout) {
  extern __shared__ __align__(16) char smem[];
  const int tid = threadIdx.x;
  const int wid = tid >> 5, lane = tid & 31;
  const int m0 = blockIdx.x * 128, n0 = blockIdx.y * 256;
  const int wm = (wid & 1) * 64, wn = (wid >> 1) * 64;
  const int cst = (MODE == 2) ? 256 : 1024;

  const __nv_bfloat16 *Ah, *Al, *Wh, *Wl;
  float* C; const float* bias = nullptr;
  if (MODE == 0) {
    int p = blockIdx.z;
    int v = c_pairv[p], wi = c_pairi[p];
    Ah = g_Ah + (size_t)v * BD;  Al = g_Al + (size_t)v * BD;
    Wh = g_Wh + (size_t)wi * DD; Wl = g_Wl + (size_t)wi * DD;
    C = g_V + (size_t)p * BD;
  } else if (MODE == 1) {
    int i = blockIdx.z;
    Ah = g_Oh + (size_t)i * BD;  Al = g_Ol + (size_t)i * BD;
    Wh = g_Wh + (size_t)(7 + i) * DD; Wl = g_Wl + (size_t)(7 + i) * DD;
    C = dout + (size_t)i * BD;
    bias = b_out + i * Dm;
  } else {
    int v = blockIdx.z;
    Ah = g_Ah + (size_t)v * BD;  Al = g_Al + (size_t)v * BD;
    Wh = g_Sh; Wl = g_Sl;
    C = g_SC + (size_t)v * Bq * 256;
  }
  const __nv_bfloat16* Aseg[3] = {Ah, Ah, Al};
  const __nv_bfloat16* Wseg[3] = {Wh, Wl, Wh};

  const uint32_t sb = smem_u32(smem);

  float acc[4][8][4];
  #pragma unroll
  for (int mt = 0; mt < 4; mt++)
    #pragma unroll
    for (int nt = 0; nt < 8; nt++)
      #pragma unroll
      for (int r = 0; r < 4; r++) acc[mt][nt][r] = 0.f;

  // loader geometry: thread t moves rows lrow of A, B0(+0), B1(+128); granules g0,g0+1
  const int lrow = tid >> 1;
  const int g0 = (tid & 1) * 2;
  const uint32_t soff0 = sw(lrow, g0);
  const uint32_t soff1 = sw(lrow, g0 + 1);

  #pragma unroll 1
  for (int c = 0; c < 3; c++) {
    int s = c >> 5, kc = (c & 31) * 32;
    const __nv_bfloat16* Ap = Aseg[s] + (size_t)(m0 + lrow) * Dm + kc;
    const __nv_bfloat16* B0 = Wseg[s] + (size_t)(n0 + lrow) * Dm + kc;
    const __nv_bfloat16* B1 = Wseg[s] + (size_t)(n0 + 128 + lrow) * Dm + kc;
    uint32_t ab = sb + c * STAGE;
    cpa16(ab + soff0,         Ap + g0 * 8);
    cpa16(ab + soff1,         Ap + g0 * 8 + 8);
    cpa16(ab + 8192 + soff0,  B0 + g0 * 8);
    cpa16(ab + 8192 + soff1,  B0 + g0 * 8 + 8);
    cpa16(ab + 16384 + soff0, B1 + g0 * 8);
    cpa16(ab + 16384 + soff1, B1 + g0 * 8 + 8);
    CP_COMMIT();
  }

  // ldmatrix lane geometry
  const int arow = wm + (lane & 15);
  const int agsel = lane >> 4;
  const int brow = wn + ((lane & 7) | ((lane & 16) >> 1));
  const int bgsel = (lane >> 3) & 1;

  for (int c = 0; c < CHUNKS; c++) {
    const uint32_t ab = sb + (c & 3) * STAGE;
    CP_WAIT2();
    __syncthreads();
    #pragma unroll
    for (int ks = 0; ks < 2; ks++) {
      uint32_t a[4][4], b[8][2];
      #pragma unroll
      for (int mt = 0; mt < 4; mt++) {
        uint32_t addr = ab + sw(arow + mt * 16, ks * 2 + agsel);
        ldsm4(a[mt][0], a[mt][1], a[mt][2], a[mt][3], addr);
      }
      #pragma unroll
      for (int np = 0; np < 4; np++) {
        uint32_t addr = ab + 8192 + sw(brow + np * 16, ks * 2 + bgsel);
        ldsm4(b[np*2][0], b[np*2][1], b[np*2+1][0], b[np*2+1][1], addr);
      }
      #pragma unroll
      for (int mt = 0; mt < 4; mt++)
        #pragma unroll
        for (int nt = 0; nt < 8; nt++)
          mma16816(acc[mt][nt], a[mt], b[nt]);
    }
    __syncthreads();
    int cn = c + 3;
    if (cn < CHUNKS) {
      int s = cn >> 5, kc = (cn & 31) * 32;
      const __nv_bfloat16* Ap = Aseg[s] + (size_t)(m0 + lrow) * Dm + kc;
      const __nv_bfloat16* B0 = Wseg[s] + (size_t)(n0 + lrow) * Dm + kc;
      const __nv_bfloat16* B1 = Wseg[s] + (size_t)(n0 + 128 + lrow) * Dm + kc;
      uint32_t nb = sb + (cn & 3) * STAGE;
      cpa16(nb + soff0,         Ap + g0 * 8);
      cpa16(nb + soff1,         Ap + g0 * 8 + 8);
      cpa16(nb + 8192 + soff0,  B0 + g0 * 8);
      cpa16(nb + 8192 + soff1,  B0 + g0 * 8 + 8);
      cpa16(nb + 16384 + soff0, B1 + g0 * 8);
      cpa16(nb + 16384 + soff1, B1 + g0 * 8 + 8);
    }
    CP_COMMIT();
  }

  // epilogue
  #pragma unroll
  for (int mt = 0; mt < 4; mt++) {
    int m = m0 + wm + mt * 16 + (lane >> 2);
    #pragma unroll
    for (int nt = 0; nt < 8; nt++) {
      int n = n0 + wn + nt * 8 + (lane & 3) * 2;
      float2 v0 = make_float2(acc[mt][nt][0], acc[mt][nt][1]);
      float2 v1 = make_float2(acc[mt][nt][2], acc[mt][nt][3]);
      if (MODE == 1) {
        float b0 = bias[n], b1 = bias[n + 1];
        v0.x += b0; v0.y += b1; v1.x += b0; v1.y += b1;
      }
      *(float2*)(C + (size_t)m * cst + n) = v0;
      *(float2*)(C + (size_t)(m + 8) * cst + n) = v1;
    }
  }
}

// ======================================================================
extern "C" void kernel_launch(void* const* d_in, const int* in_sizes, int n_in,
                              void* d_out, int out_size) {
  const float* xc     = (const float*)d_in[0];
  const float* xf     = (const float*)d_in[1];
  const float* xbd    = (const float*)d_in[2];
  const float* xbg    = (const float*)d_in[3];
  const float* tokens = (const float*)d_in[4];
  const float* w_in   = (const float*)d_in[5];
  const float* b_in   = (const float*)d_in[6];
  const float* w_out  = (const float*)d_in[7];
  const float* b_out  = (const float*)d_in[8];
  float* out = (float*)d_out;

  cudaFuncSetAttribute(k_mma<0>, cudaFuncAttributeMaxDynamicSharedMemorySize, SMEM_SZ);
  cudaFuncSetAttribute(k_mma<1>, cudaFuncAttributeMaxDynamicSharedMemorySize, SMEM_SZ);
  cudaFuncSetAttribute(k_mma<2>, cudaFuncAttributeMaxDynamicSharedMemorySize, SMEM_SZ);

  k_qh<<<NBR, 256>>>(tokens, w_in, b_in);
  k_s<<<dim3(NBR, 8), 256>>>(w_in);
  k_zs<<<144, 256>>>();
  k_convA<<<dim3(Bq, 4), 256>>>(xc, xf, xbd, xbg);
  k_mma<2><<<dim3(Bq / 128, 1, 4), 256, SMEM_SZ>>>(b_out, out);
  k_softmax<<<NBR * Bq * 16 / 256, 256>>>();
  k_convW<<<dim3(1024, 14), 256>>>(w_in, w_out);
  k_mma<0><<<dim3(Bq / 128, Dm / 256, 19), 256, SMEM_SZ>>>(b_out, out);
  k_mix<<<NBR * Bq * (Dm / 4) / 256, 256>>>(b_in);
  k_mma<1><<<dim3(Bq / 128, Dm / 256, NBR), 256, SMEM_SZ>>>(b_out, out);
}

// round 6
// speedup vs baseline: 2.9948x; 1.5726x over previous
#include <cuda_runtime.h>
#include <cuda_bf16.h>
#include <cstdint>

#define Bq 8192
#define Dm 1024
#define NBR 7
#define BD ((size_t)Bq * Dm)
#define DD ((size_t)Dm * Dm)

// ---------------- scratch (tiled, pre-swizzled bf16 planes: [kc][rows][32]) ----------------
__device__ float g_Q[NBR * Dm];
__device__ float g_SC[(size_t)4 * Bq * 256];
__device__ float g_A[(size_t)NBR * 4 * Bq * 16];
__device__ float g_V[(size_t)19 * BD];
__device__ __align__(16) __nv_bfloat16 g_Sh[256 * Dm];
__device__ __align__(16) __nv_bfloat16 g_Sl[256 * Dm];
__device__ __align__(16) __nv_bfloat16 g_Ah[4 * BD];
__device__ __align__(16) __nv_bfloat16 g_Al[4 * BD];
__device__ __align__(16) __nv_bfloat16 g_Wh[14 * DD];
__device__ __align__(16) __nv_bfloat16 g_Wl[14 * DD];
__device__ __align__(16) __nv_bfloat16 g_Oh[NBR * BD];
__device__ __align__(16) __nv_bfloat16 g_Ol[NBR * BD];

__constant__ int c_nvec[NBR] = {2,2,2,3,3,3,4};
__constant__ int c_vidx[NBR][4] = {{0,1,0,0},{0,2,0,0},{0,3,0,0},{0,1,2,0},{0,1,3,0},{0,2,3,0},{0,1,2,3}};
__constant__ int c_poff[NBR] = {0,2,4,6,9,12,15};
__constant__ int c_pairi[19] = {0,0,1,1,2,2,3,3,3,4,4,4,5,5,5,6,6,6,6};
__constant__ int c_pairv[19] = {0,1,0,2,0,3,0,1,2,0,1,3,0,2,3,0,1,2,3};

// tiled+swizzled element offset within a [R rows x 1024 k] plane
__device__ __forceinline__ size_t toff(int row, int k, int R) {
  return ((size_t)(k >> 5) * R + row) * 32 +
         (((((k >> 3) & 3) ^ ((row >> 1) & 3)) << 3) + (k & 7));
}

// ---------------- PTX helpers ----------------
__device__ __forceinline__ uint32_t smem_u32(const void* p) {
  uint32_t a;
  asm("{ .reg .u64 t; cvta.to.shared.u64 t, %1; cvt.u32.u64 %0, t; }" : "=r"(a) : "l"(p));
  return a;
}
#define MBAR_INIT(a, n) asm volatile("mbarrier.init.shared.b64 [%0], %1;" :: "r"(a), "r"(n) : "memory")
#define MBAR_EXPECT(a, b) asm volatile("mbarrier.arrive.expect_tx.shared.b64 _, [%0], %1;" :: "r"(a), "r"(b) : "memory")
#define MBAR_WAIT(a, ph) do { \
  uint32_t _m = (a), _p = (ph), _d; \
  asm volatile("{ .reg .pred p; mbarrier.try_wait.parity.acquire.cta.shared::cta.b64 p, [%1], %2; selp.b32 %0,1,0,p; }" \
    : "=r"(_d) : "r"(_m), "r"(_p) : "memory"); \
  if (!_d) { asm volatile("{ .reg .pred P1; WL_%=: mbarrier.try_wait.parity.acquire.cta.shared::cta.b64 P1, [%0], %1, 0x989680; @P1 bra.uni WD_%=; bra.uni WL_%=; WD_%=: }" \
    :: "r"(_m), "r"(_p) : "memory"); } } while (0)

__device__ __forceinline__ void bulk_g2s(uint32_t dst, const void* src, uint32_t bytes, uint32_t mbar) {
  asm volatile("cp.async.bulk.shared::cluster.global.mbarrier::complete_tx::bytes [%0], [%1], %2, [%3];"
               :: "r"(dst), "l"(src), "r"(bytes), "r"(mbar) : "memory");
}
__device__ __forceinline__ void ldsm4(uint32_t& r0, uint32_t& r1, uint32_t& r2, uint32_t& r3, uint32_t addr) {
  asm volatile("ldmatrix.sync.aligned.m8n8.x4.shared.b16 {%0,%1,%2,%3}, [%4];"
               : "=r"(r0), "=r"(r1), "=r"(r2), "=r"(r3) : "r"(addr));
}
__device__ __forceinline__ void mma16816(float* c, const uint32_t* a, const uint32_t* b) {
  asm volatile("mma.sync.aligned.m16n8k16.row.col.f32.bf16.bf16.f32 "
               "{%0,%1,%2,%3}, {%4,%5,%6,%7}, {%8,%9}, {%0,%1,%2,%3};"
               : "+f"(c[0]), "+f"(c[1]), "+f"(c[2]), "+f"(c[3])
               : "r"(a[0]), "r"(a[1]), "r"(a[2]), "r"(a[3]), "r"(b[0]), "r"(b[1]));
}

// ======================= fp32 -> bf16 hi/lo split =======================
__device__ __forceinline__ void split4(float4 v, uint2& hi, uint2& lo) {
  __nv_bfloat16 h0 = __float2bfloat16_rn(v.x), h1 = __float2bfloat16_rn(v.y);
  __nv_bfloat16 h2 = __float2bfloat16_rn(v.z), h3 = __float2bfloat16_rn(v.w);
  __nv_bfloat16 l0 = __float2bfloat16_rn(v.x - __bfloat162float(h0));
  __nv_bfloat16 l1 = __float2bfloat16_rn(v.y - __bfloat162float(h1));
  __nv_bfloat16 l2 = __float2bfloat16_rn(v.z - __bfloat162float(h2));
  __nv_bfloat16 l3 = __float2bfloat16_rn(v.w - __bfloat162float(h3));
  __nv_bfloat162 a{h0, h1}, b{h2, h3}, c{l0, l1}, d{l2, l3};
  hi = make_uint2(*(uint32_t*)&a, *(uint32_t*)&b);
  lo = make_uint2(*(uint32_t*)&c, *(uint32_t*)&d);
}

// ======================= prep / conversion kernels =======================
__global__ void k_qh(const float* __restrict__ tokens, const float* __restrict__ w_in,
                     const float* __restrict__ b_in) {
  int i = blockIdx.x, t = threadIdx.x;
  __shared__ float tok[Dm];
  for (int k = t; k < Dm; k += 256) tok[k] = tokens[i * Dm + k];
  __syncthreads();
  const float* wq = w_in + (size_t)i * 3 * DD;
  for (int r = t; r < Dm; r += 256) {
    const float* row = wq + (size_t)r * Dm;
    float acc = b_in[i * 3 * Dm + r];
    for (int k = 0; k < Dm; k += 4) {
      float4 w = *(const float4*)(row + k);
      acc += w.x*tok[k] + w.y*tok[k+1] + w.z*tok[k+2] + w.w*tok[k+3];
    }
    g_Q[i * Dm + r] = acc;
  }
}

__global__ void k_zs() {   // zero all of g_Sh/g_Sl (zeros are swizzle-invariant)
  size_t i = ((size_t)blockIdx.x * 256 + threadIdx.x) * 4;
  *(uint2*)(g_Sh + i) = make_uint2(0, 0);
  *(uint2*)(g_Sl + i) = make_uint2(0, 0);
}

__global__ void k_s(const float* __restrict__ w_in) {
  int i = blockIdx.x, kb = blockIdx.y * 128;
  __shared__ float qh[Dm];
  for (int k = threadIdx.x; k < Dm; k += 256) qh[k] = g_Q[i * Dm + k];
  __syncthreads();
  const float* wk = w_in + (size_t)i * 3 * DD + DD;
  for (int o = threadIdx.x; o < 16 * 128; o += 256) {
    int h = o >> 7, k = kb + (o & 127);
    float acc = 0.f;
    #pragma unroll 8
    for (int j = 0; j < 64; j++) acc += wk[(size_t)(h * 64 + j) * Dm + k] * qh[h * 64 + j];
    float val = 0.125f * acc;
    __nv_bfloat16 hi = __float2bfloat16_rn(val);
    size_t off = toff(i * 16 + h, k, 256);
    g_Sh[off] = hi;
    g_Sl[off] = __float2bfloat16_rn(val - __bfloat162float(hi));
  }
}

__global__ void k_softmax() {
  int idx = blockIdx.x * 256 + threadIdx.x;
  int h = idx & 15;
  int b = (idx >> 4) & (Bq - 1);
  int i = idx >> 17;
  int L = c_nvec[i];
  float sc[4];
  float mx = -1e30f;
  #pragma unroll
  for (int l = 0; l < 4; l++) if (l < L) {
    sc[l] = g_SC[((size_t)c_vidx[i][l] * Bq + b) * 256 + i * 16 + h];
    mx = fmaxf(mx, sc[l]);
  }
  float sum = 0.f;
  #pragma unroll
  for (int l = 0; l < 4; l++) if (l < L) { sc[l] = expf(sc[l] - mx); sum += sc[l]; }
  float inv = 1.f / sum;
  #pragma unroll
  for (int l = 0; l < 4; l++) if (l < L)
    g_A[(((size_t)i * 4 + l) * Bq + b) * 16 + h] = sc[l] * inv;
}

__global__ void k_mix(const float* __restrict__ b_in) {
  size_t gid = (size_t)blockIdx.x * 256 + threadIdx.x;
  int i = (int)(gid >> 21);
  int rem = (int)(gid & ((1u << 21) - 1));
  int b = rem >> 8;
  int k = (rem & 255) * 4;
  int h = k >> 6;
  int L = c_nvec[i];
  int p0 = c_poff[i];
  float4 o = *(const float4*)(b_in + ((size_t)i * 3 + 2) * Dm + k);
  #pragma unroll
  for (int l = 0; l < 4; l++) if (l < L) {
    float a = g_A[(((size_t)i * 4 + l) * Bq + b) * 16 + h];
    float4 vv = *(const float4*)(g_V + ((size_t)(p0 + l) * Bq + b) * Dm + k);
    o.x += a * vv.x; o.y += a * vv.y; o.z += a * vv.z; o.w += a * vv.w;
  }
  uint2 hi, lo; split4(o, hi, lo);
  size_t off = (size_t)i * BD + toff(b, k, Bq);
  *(uint2*)(g_Oh + off) = hi;
  *(uint2*)(g_Ol + off) = lo;
}

__global__ void k_convA(const float* __restrict__ xc, const float* __restrict__ xf,
                        const float* __restrict__ xbd, const float* __restrict__ xbg) {
  int v = blockIdx.y;
  const float* x = (v == 0) ? xc : (v == 1) ? xf : (v == 2) ? xbd : xbg;
  size_t i = (size_t)blockIdx.x * 256 + threadIdx.x;
  int m = (int)(i >> 8), k = ((int)i & 255) * 4;
  float4 val = ((const float4*)x)[i];
  uint2 hi, lo; split4(val, hi, lo);
  size_t off = (size_t)v * BD + toff(m, k, Bq);
  *(uint2*)(g_Ah + off) = hi;
  *(uint2*)(g_Al + off) = lo;
}

__global__ void k_convW(const float* __restrict__ w_in, const float* __restrict__ w_out) {
  int z = blockIdx.y;
  const float* src = (z < 7) ? (w_in + (size_t)z * 3 * DD + 2 * DD) : (w_out + (size_t)(z - 7) * DD);
  size_t i = (size_t)blockIdx.x * 256 + threadIdx.x;
  int n = (int)(i >> 8), k = ((int)i & 255) * 4;
  float4 val = ((const float4*)src)[i];
  uint2 hi, lo; split4(val, hi, lo);
  size_t off = (size_t)z * DD + toff(n, k, Dm);
  *(uint2*)(g_Wh + off) = hi;
  *(uint2*)(g_Wl + off) = lo;
}

// ======================= bulk-copy HMMA GEMM =======================
// CTA 128(M) x 256(N), 8 warps 64x64, K-chunk 32, 4-stage mbarrier+cp.async.bulk pipeline.
// Per chunk SMEM stage: Ah 8K | Al 8K | Bh 16K | Bl 16K = 48KB. 3 split terms per chunk.
#define NCH 32
#define STAGE 49152
#define SMEM_SZ (1024 + 4 * STAGE)

__device__ __forceinline__ uint32_t sw(uint32_t row, uint32_t g) {
  return row * 64 + ((g ^ ((row >> 1) & 3)) << 4);
}

template<int MODE>
__global__ void __launch_bounds__(256, 1) k_mma(const float* __restrict__ b_out,
                                                float* __restrict__ dout) {
  extern __shared__ __align__(128) char smem[];
  const uint32_t sb = smem_u32(smem);
  const int tid = threadIdx.x;
  const int wid = tid >> 5, lane = tid & 31;
  const int m0 = blockIdx.x * 128;
  const int n0 = (MODE == 2) ? 0 : blockIdx.y * 256;
  const int wm = (wid & 1) * 64, wn = (wid >> 1) * 64;
  const int cst = (MODE == 2) ? 256 : 1024;
  const int BN = (MODE == 2) ? 256 : 1024;     // rows per k-plane of B

  const __nv_bfloat16 *Ah, *Al, *Bh, *Bl;
  float* C; const float* bias = nullptr;
  if (MODE == 0) {
    int p = blockIdx.z;
    int v = c_pairv[p], wi = c_pairi[p];
    Ah = g_Ah + (size_t)v * BD;  Al = g_Al + (size_t)v * BD;
    Bh = g_Wh + (size_t)wi * DD; Bl = g_Wl + (size_t)wi * DD;
    C = g_V + (size_t)p * BD;
  } else if (MODE == 1) {
    int i = blockIdx.z;
    Ah = g_Oh + (size_t)i * BD;  Al = g_Ol + (size_t)i * BD;
    Bh = g_Wh + (size_t)(7 + i) * DD; Bl = g_Wl + (size_t)(7 + i) * DD;
    C = dout + (size_t)i * BD;
    bias = b_out + i * Dm;
  } else {
    int v = blockIdx.z;
    Ah = g_Ah + (size_t)v * BD;  Al = g_Al + (size_t)v * BD;
    Bh = g_Sh; Bl = g_Sl;
    C = g_SC + (size_t)v * Bq * 256;
  }

  if (tid == 0) {
    #pragma unroll
    for (int s = 0; s < 4; s++) MBAR_INIT(sb + s * 8, 1);
  }
  __syncthreads();

  // issue helper (macro-style lambda)
  auto issue = [&](int c, int s) {
    uint32_t st = sb + 1024 + s * STAGE;
    uint32_t mb = sb + s * 8;
    MBAR_EXPECT(mb, STAGE);
    bulk_g2s(st,         Ah + ((size_t)c * Bq + m0) * 32, 8192, mb);
    bulk_g2s(st + 8192,  Al + ((size_t)c * Bq + m0) * 32, 8192, mb);
    bulk_g2s(st + 16384, Bh + ((size_t)c * BN + n0) * 32, 16384, mb);
    bulk_g2s(st + 32768, Bl + ((size_t)c * BN + n0) * 32, 16384, mb);
  };

  if (tid == 0) {
    #pragma unroll
    for (int c = 0; c < 4; c++) issue(c, c);
  }

  float acc[4][8][4];
  #pragma unroll
  for (int mt = 0; mt < 4; mt++)
    #pragma unroll
    for (int nt = 0; nt < 8; nt++)
      #pragma unroll
      for (int r = 0; r < 4; r++) acc[mt][nt][r] = 0.f;

  const int arow = wm + (lane & 15);
  const int agsel = lane >> 4;
  const int brow = wn + ((lane & 7) | ((lane & 16) >> 1));
  const int bgsel = (lane >> 3) & 1;

  for (int c = 0; c < NCH; c++) {
    const int s = c & 3;
    const uint32_t st = sb + 1024 + s * STAGE;
    MBAR_WAIT(sb + s * 8, (c >> 2) & 1);
    #pragma unroll
    for (int ks = 0; ks < 2; ks++) {
      uint32_t ah[4][4], al[4][4];
      #pragma unroll
      for (int mt = 0; mt < 4; mt++) {
        uint32_t ad = st + sw(arow + mt * 16, ks * 2 + agsel);
        ldsm4(ah[mt][0], ah[mt][1], ah[mt][2], ah[mt][3], ad);
      }
      #pragma unroll
      for (int mt = 0; mt < 4; mt++) {
        uint32_t ad = st + 8192 + sw(arow + mt * 16, ks * 2 + agsel);
        ldsm4(al[mt][0], al[mt][1], al[mt][2], al[mt][3], ad);
      }
      #pragma unroll
      for (int half = 0; half < 2; half++) {
        uint32_t bh[4][2], bl[4][2];
        #pragma unroll
        for (int np = 0; np < 2; np++) {
          uint32_t bd = st + 16384 + sw(brow + (half * 2 + np) * 16, ks * 2 + bgsel);
          ldsm4(bh[np*2][0], bh[np*2][1], bh[np*2+1][0], bh[np*2+1][1], bd);
          bd = st + 32768 + sw(brow + (half * 2 + np) * 16, ks * 2 + bgsel);
          ldsm4(bl[np*2][0], bl[np*2][1], bl[np*2+1][0], bl[np*2+1][1], bd);
        }
        #pragma unroll
        for (int mt = 0; mt < 4; mt++)
          #pragma unroll
          for (int ntl = 0; ntl < 4; ntl++) {
            int nt = half * 4 + ntl;
            mma16816(acc[mt][nt], ah[mt], bh[ntl]);
            mma16816(acc[mt][nt], ah[mt], bl[ntl]);
            mma16816(acc[mt][nt], al[mt], bh[ntl]);
          }
      }
    }
    __syncthreads();
    if (tid == 0 && c + 4 < NCH) issue(c + 4, s);
  }

  // epilogue
  #pragma unroll
  for (int mt = 0; mt < 4; mt++) {
    int m = m0 + wm + mt * 16 + (lane >> 2);
    #pragma unroll
    for (int nt = 0; nt < 8; nt++) {
      int n = n0 + wn + nt * 8 + (lane & 3) * 2;
      float2 v0 = make_float2(acc[mt][nt][0], acc[mt][nt][1]);
      float2 v1 = make_float2(acc[mt][nt][2], acc[mt][nt][3]);
      if (MODE == 1) {
        float b0 = bias[n], b1 = bias[n + 1];
        v0.x += b0; v0.y += b1; v1.x += b0; v1.y += b1;
      }
      *(float2*)(C + (size_t)m * cst + n) = v0;
      *(float2*)(C + (size_t)(m + 8) * cst + n) = v1;
    }
  }
}

// ======================================================================
extern "C" void kernel_launch(void* const* d_in, const int* in_sizes, int n_in,
                              void* d_out, int out_size) {
  const float* xc     = (const float*)d_in[0];
  const float* xf     = (const float*)d_in[1];
  const float* xbd    = (const float*)d_in[2];
  const float* xbg    = (const float*)d_in[3];
  const float* tokens = (const float*)d_in[4];
  const float* w_in   = (const float*)d_in[5];
  const float* b_in   = (const float*)d_in[6];
  const float* w_out  = (const float*)d_in[7];
  const float* b_out  = (const float*)d_in[8];
  float* out = (float*)d_out;

  cudaFuncSetAttribute(k_mma<0>, cudaFuncAttributeMaxDynamicSharedMemorySize, SMEM_SZ);
  cudaFuncSetAttribute(k_mma<1>, cudaFuncAttributeMaxDynamicSharedMemorySize, SMEM_SZ);
  cudaFuncSetAttribute(k_mma<2>, cudaFuncAttributeMaxDynamicSharedMemorySize, SMEM_SZ);

  k_convA<<<dim3(Bq, 4), 256>>>(xc, xf, xbd, xbg);                       // 0
  k_convW<<<dim3(1024, 14), 256>>>(w_in, w_out);                         // 1
  k_qh<<<NBR, 256>>>(tokens, w_in, b_in);                                // 2
  k_mma<0><<<dim3(Bq/128, Dm/256, 19), 256, SMEM_SZ>>>(b_out, out);      // 3  <- ncu capture slot
  k_zs<<<256, 256>>>();                                                  // 4
  k_s<<<dim3(NBR, 8), 256>>>(w_in);                                      // 5
  k_mma<2><<<dim3(Bq/128, 1, 4), 256, SMEM_SZ>>>(b_out, out);            // 6
  k_softmax<<<NBR * Bq * 16 / 256, 256>>>();                             // 7
  k_mix<<<NBR * Bq * (Dm / 4) / 256, 256>>>(b_in);                       // 8
  k_mma<1><<<dim3(Bq/128, Dm/256, NBR), 256, SMEM_SZ>>>(b_out, out);     // 9
}